// round 14
// baseline (speedup 1.0000x reference)
#include <cuda_runtime.h>
#include <cuda_fp16.h>
#include <math.h>
#include <stdint.h>

// Problem constants
#define BB 2
#define NN 2048
#define CC 1024
#define HH 16
#define DH 64
#define MLPD 4096
#define MM (BB*NN)          // 4096 tokens
#define C3 (3*CC)           // 3072

// ---------------- scratch (static device globals; no allocation) ----------------
__device__ __half g_x1[MM*CC];       // x + pos (fp16 residual)
__device__ __half g_x2[MM*CC];       // after attn residual (fp16)
__device__ __half g_h[MM*CC];        // LN1 out
__device__ __half g_qkv[MM*C3];      // qkv (lora folded into weights)
__device__ __half g_attn[MM*CC];     // attention out
__device__ __half g_h2[MM*CC];       // LN2 out
__device__ __half g_mlp[MM*MLPD];    // gelu(...)
__device__ __half g_wqkv_h[C3*CC];   // Wqkv + 0.25*B@A folded, fp16
__device__ __half g_wproj_h[CC*CC];
__device__ __half g_w1_h[MLPD*CC];
__device__ __half g_w2_h[CC*MLPD];

#define CP_ASYNC16(dst, src) \
    asm volatile("cp.async.ca.shared.global [%0], [%1], 16;" :: "r"(dst), "l"(src))
#define CP_COMMIT() asm volatile("cp.async.commit_group;")
#define CP_WAIT(n)  asm volatile("cp.async.wait_group %0;" :: "n"(n))

#define LDMATRIX_X4(r0, r1, r2, r3, addr) \
    asm volatile("ldmatrix.sync.aligned.m8n8.x4.shared.b16 {%0,%1,%2,%3}, [%4];" \
                 : "=r"(r0), "=r"(r1), "=r"(r2), "=r"(r3) : "r"(addr))
#define LDMATRIX_X4_T(r0, r1, r2, r3, addr) \
    asm volatile("ldmatrix.sync.aligned.m8n8.x4.trans.shared.b16 {%0,%1,%2,%3}, [%4];" \
                 : "=r"(r0), "=r"(r1), "=r"(r2), "=r"(r3) : "r"(addr))

#define MMA_F16(c0, c1, c2, c3, a0, a1, a2, a3, b0, b1) \
    asm volatile("mma.sync.aligned.m16n8k16.row.col.f32.f16.f16.f32 " \
                 "{%0,%1,%2,%3}, {%4,%5,%6,%7}, {%8,%9}, {%0,%1,%2,%3};" \
                 : "+f"(c0), "+f"(c1), "+f"(c2), "+f"(c3) \
                 : "r"(a0), "r"(a1), "r"(a2), "r"(a3), "r"(b0), "r"(b1))

// ---------------- fp32 -> fp16 weight conversion ----------------
__global__ void f2h_kernel(const float* __restrict__ in,
                           __half* __restrict__ out, int n8) {
    int i = blockIdx.x * blockDim.x + threadIdx.x;
    if (i < n8) {
        float4 a = ((const float4*)in)[2 * i];
        float4 b = ((const float4*)in)[2 * i + 1];
        __half2 h[4];
        h[0] = __floats2half2_rn(a.x, a.y);
        h[1] = __floats2half2_rn(a.z, a.w);
        h[2] = __floats2half2_rn(b.x, b.y);
        h[3] = __floats2half2_rn(b.z, b.w);
        ((uint4*)out)[i] = *(uint4*)h;
    }
}

// ---------------- Wqkv conversion with LoRA rank-4 fold ----------------
__global__ void wqkv_fold_f2h_kernel(const float* __restrict__ W,
                                     const float* __restrict__ loraA,   // [8,1024]
                                     const float* __restrict__ loraB,   // [2048,4]
                                     __half* __restrict__ out) {
    int idx = blockIdx.x * blockDim.x + threadIdx.x;   // < 3072*1024/8
    if (idx >= C3 * CC / 8) return;
    int i = idx >> 7;              // row 0..3071
    int j0 = (idx & 127) * 8;      // col block
    float4 a = ((const float4*)(W + (size_t)i * CC + j0))[0];
    float4 b = ((const float4*)(W + (size_t)i * CC + j0))[1];
    float w[8] = {a.x, a.y, a.z, a.w, b.x, b.y, b.z, b.w};
    int aoff = -1, brow = -1;
    if (i < CC)            { aoff = 0; brow = i; }
    else if (i >= 2 * CC)  { aoff = 4; brow = CC + (i - 2 * CC); }
    if (aoff >= 0) {
        float br[4];
#pragma unroll
        for (int r = 0; r < 4; r++) br[r] = loraB[brow * 4 + r];
#pragma unroll
        for (int jj = 0; jj < 8; jj++) {
            float d = 0.f;
#pragma unroll
            for (int r = 0; r < 4; r++)
                d = fmaf(br[r], loraA[(aoff + r) * CC + j0 + jj], d);
            w[jj] += 0.25f * d;
        }
    }
    __half2 h[4];
#pragma unroll
    for (int p = 0; p < 4; p++) h[p] = __floats2half2_rn(w[2 * p], w[2 * p + 1]);
    ((uint4*)out)[idx] = *(uint4*)h;
}

// ---------------- fused (x+pos) + LayerNorm -> fp16 (fp32 input; also writes fp16 x1) ----------------
__global__ void addpos_ln_kernel(const float* __restrict__ x,
                                 const float* __restrict__ pos,
                                 const float* __restrict__ g,
                                 const float* __restrict__ b,
                                 __half* __restrict__ x1out,
                                 __half* __restrict__ hout) {
    int row = blockIdx.x;
    int t = threadIdx.x;
    int warp = t >> 5, lane = t & 31;
    float4 v4 = ((const float4*)(x + (size_t)row * CC))[t];
    float4 p4 = ((const float4*)(pos + (size_t)row * CC))[t];
    v4.x += p4.x; v4.y += p4.y; v4.z += p4.z; v4.w += p4.w;
    {
        __half2 a01 = __floats2half2_rn(v4.x, v4.y);
        __half2 a23 = __floats2half2_rn(v4.z, v4.w);
        uint2 pk = make_uint2(*(uint32_t*)&a01, *(uint32_t*)&a23);
        ((uint2*)(x1out + (size_t)row * CC))[t] = pk;
    }

    __shared__ float swred[8];
    __shared__ float bc[2];
    float s = v4.x + v4.y + v4.z + v4.w;
#pragma unroll
    for (int o = 16; o > 0; o >>= 1) s += __shfl_xor_sync(0xffffffffu, s, o);
    if (lane == 0) swred[warp] = s;
    __syncthreads();
    if (t == 0) {
        float tot = 0.f;
#pragma unroll
        for (int w = 0; w < 8; w++) tot += swred[w];
        bc[0] = tot * (1.0f / CC);
    }
    __syncthreads();
    float mean = bc[0];
    float dx = v4.x - mean, dy = v4.y - mean, dz = v4.z - mean, dw = v4.w - mean;
    float sq = dx * dx + dy * dy + dz * dz + dw * dw;
#pragma unroll
    for (int o = 16; o > 0; o >>= 1) sq += __shfl_xor_sync(0xffffffffu, sq, o);
    if (lane == 0) swred[warp] = sq;
    __syncthreads();
    if (t == 0) {
        float tot = 0.f;
#pragma unroll
        for (int w = 0; w < 8; w++) tot += swred[w];
        bc[1] = rsqrtf(tot * (1.0f / CC) + 1e-5f);
    }
    __syncthreads();
    float rstd = bc[1];
    float4 g4 = ((const float4*)g)[t];
    float4 b4 = ((const float4*)b)[t];
    __half2 h01 = __floats2half2_rn(dx * rstd * g4.x + b4.x, dy * rstd * g4.y + b4.y);
    __half2 h23 = __floats2half2_rn(dz * rstd * g4.z + b4.z, dw * rstd * g4.w + b4.w);
    uint2 pk = make_uint2(*(uint32_t*)&h01, *(uint32_t*)&h23);
    ((uint2*)(hout + (size_t)row * CC))[t] = pk;
}

// ---------------- LayerNorm on fp16 input -> fp16 (for LN2; stats in fp32) ----------------
__global__ void ln_h_kernel(const __half* __restrict__ x,
                            const float* __restrict__ g,
                            const float* __restrict__ b,
                            __half* __restrict__ hout) {
    int row = blockIdx.x;
    int t = threadIdx.x;
    int warp = t >> 5, lane = t & 31;
    uint2 pk = ((const uint2*)(x + (size_t)row * CC))[t];
    __half2 a01 = *(__half2*)&pk.x;
    __half2 a23 = *(__half2*)&pk.y;
    float4 v4;
    { float2 f01 = __half22float2(a01); float2 f23 = __half22float2(a23);
      v4.x = f01.x; v4.y = f01.y; v4.z = f23.x; v4.w = f23.y; }

    __shared__ float swred[8];
    __shared__ float bc[2];
    float s = v4.x + v4.y + v4.z + v4.w;
#pragma unroll
    for (int o = 16; o > 0; o >>= 1) s += __shfl_xor_sync(0xffffffffu, s, o);
    if (lane == 0) swred[warp] = s;
    __syncthreads();
    if (t == 0) {
        float tot = 0.f;
#pragma unroll
        for (int w = 0; w < 8; w++) tot += swred[w];
        bc[0] = tot * (1.0f / CC);
    }
    __syncthreads();
    float mean = bc[0];
    float dx = v4.x - mean, dy = v4.y - mean, dz = v4.z - mean, dw = v4.w - mean;
    float sq = dx * dx + dy * dy + dz * dz + dw * dw;
#pragma unroll
    for (int o = 16; o > 0; o >>= 1) sq += __shfl_xor_sync(0xffffffffu, sq, o);
    if (lane == 0) swred[warp] = sq;
    __syncthreads();
    if (t == 0) {
        float tot = 0.f;
#pragma unroll
        for (int w = 0; w < 8; w++) tot += swred[w];
        bc[1] = rsqrtf(tot * (1.0f / CC) + 1e-5f);
    }
    __syncthreads();
    float rstd = bc[1];
    float4 g4 = ((const float4*)g)[t];
    float4 b4 = ((const float4*)b)[t];
    __half2 h01 = __floats2half2_rn(dx * rstd * g4.x + b4.x, dy * rstd * g4.y + b4.y);
    __half2 h23 = __floats2half2_rn(dz * rstd * g4.z + b4.z, dw * rstd * g4.w + b4.w);
    uint2 po = make_uint2(*(uint32_t*)&h01, *(uint32_t*)&h23);
    ((uint2*)(hout + (size_t)row * CC))[t] = po;
}

// ---------------- fp16 tensor-core GEMM (round-4 proven; res is fp16 now) ----------------
__global__ void __launch_bounds__(256)
gemm_f16_kernel(const __half* __restrict__ A, const __half* __restrict__ B,
                const float* __restrict__ bias, const __half* __restrict__ res,
                float* __restrict__ outf, __half* __restrict__ outh,
                int M, int Ncols, int K, int act) {
    extern __shared__ char smc[];
    uint32_t smbase = (uint32_t)__cvta_generic_to_shared(smc);
    const int tid = threadIdx.x;
    const int lane = tid & 31;
    const int warp = tid >> 5;
    const int warp_m = warp & 1;
    const int warp_n = warp >> 1;
    const int bm = blockIdx.y * 128;
    const int bn = blockIdx.x * 128;

    const int a_lrow = lane & 15;
    const int a_lch  = lane >> 4;
    const int b_nrow = (lane & 7) + ((lane >> 4) << 3);
    const int b_kc   = (lane & 8) >> 3;

    float acc[4][4][4];
#pragma unroll
    for (int i = 0; i < 4; i++)
#pragma unroll
        for (int j = 0; j < 4; j++)
#pragma unroll
            for (int r = 0; r < 4; r++) acc[i][j][r] = 0.f;

    const int Ksteps = K >> 6;   // K/64

    auto load_tile = [&](int s, int kk) {
        uint32_t a_base = smbase + s * 16384;
        uint32_t b_base = smbase + 32768 + s * 16384;
#pragma unroll
        for (int i = 0; i < 4; i++) {
            int id = tid + i * 256;
            int row = id >> 3, ch = id & 7;
            const __half* srcA = A + (size_t)(bm + row) * K + kk + ch * 8;
            uint32_t dstA = a_base + row * 128 + ((ch ^ (row & 7)) << 4);
            CP_ASYNC16(dstA, srcA);
        }
#pragma unroll
        for (int i = 0; i < 4; i++) {
            int id = tid + i * 256;
            int row = id >> 3, ch = id & 7;
            const __half* srcB = B + (size_t)(bn + row) * K + kk + ch * 8;
            uint32_t dstB = b_base + row * 128 + ((ch ^ (row & 7)) << 4);
            CP_ASYNC16(dstB, srcB);
        }
    };

    load_tile(0, 0);
    CP_COMMIT();

    for (int s = 0; s < Ksteps; s++) {
        int buf = s & 1;
        if (s + 1 < Ksteps) {
            load_tile(buf ^ 1, (s + 1) << 6);
            CP_COMMIT();
            CP_WAIT(1);
        } else {
            CP_WAIT(0);
        }
        __syncthreads();

        uint32_t a_base = smbase + buf * 16384;
        uint32_t b_base = smbase + 32768 + buf * 16384;

#pragma unroll
        for (int ks = 0; ks < 4; ks++) {
            uint32_t af[4][4];
#pragma unroll
            for (int mt = 0; mt < 4; mt++) {
                int m = warp_m * 64 + mt * 16 + a_lrow;
                int chunk = ks * 2 + a_lch;
                uint32_t addr = a_base + m * 128 + ((chunk ^ (m & 7)) << 4);
                LDMATRIX_X4(af[mt][0], af[mt][1], af[mt][2], af[mt][3], addr);
            }
            uint32_t bf[2][4];
#pragma unroll
            for (int p = 0; p < 2; p++) {
                int n = warp_n * 32 + p * 16 + b_nrow;
                int chunk = ks * 2 + b_kc;
                uint32_t addr = b_base + n * 128 + ((chunk ^ (n & 7)) << 4);
                LDMATRIX_X4(bf[p][0], bf[p][1], bf[p][2], bf[p][3], addr);
            }
#pragma unroll
            for (int mt = 0; mt < 4; mt++)
#pragma unroll
                for (int nt = 0; nt < 4; nt++) {
                    uint32_t b0 = bf[nt >> 1][(nt & 1) * 2];
                    uint32_t b1 = bf[nt >> 1][(nt & 1) * 2 + 1];
                    MMA_F16(acc[mt][nt][0], acc[mt][nt][1], acc[mt][nt][2], acc[mt][nt][3],
                            af[mt][0], af[mt][1], af[mt][2], af[mt][3], b0, b1);
                }
        }
        __syncthreads();
    }

    const int gid = lane >> 2;
    const int tig = lane & 3;
#pragma unroll
    for (int mt = 0; mt < 4; mt++) {
#pragma unroll
        for (int nt = 0; nt < 4; nt++) {
            int col = bn + warp_n * 32 + nt * 8 + tig * 2;
            float bi0 = bias[col], bi1 = bias[col + 1];
#pragma unroll
            for (int half_i = 0; half_i < 2; half_i++) {
                int row = bm + warp_m * 64 + mt * 16 + gid + half_i * 8;
                float v0 = acc[mt][nt][half_i * 2 + 0] + bi0;
                float v1 = acc[mt][nt][half_i * 2 + 1] + bi1;
                if (act == 1) {
                    v0 = 0.5f * v0 * (1.0f + erff(v0 * 0.70710678118654752f));
                    v1 = 0.5f * v1 * (1.0f + erff(v1 * 0.70710678118654752f));
                }
                if (res) {
                    __half2 rv = *(const __half2*)&res[(size_t)row * Ncols + col];
                    float2 rf = __half22float2(rv);
                    v0 += rf.x;
                    v1 += rf.y;
                }
                if (outh) {
                    __half2 hv = __floats2half2_rn(v0, v1);
                    *(__half2*)&outh[(size_t)row * Ncols + col] = hv;
                } else {
                    float2 ov = make_float2(v0, v1);
                    *(float2*)&outf[(size_t)row * Ncols + col] = ov;
                }
            }
        }
    }
}

// ---------------- fp16 TC flash attention: 128 q-rows, 4 warps (32 q-rows/warp), register P ----------------
// smem: Q [0,16K) K0 [16K,24K) K1 [24K,32K) V0 [32K,40K) V1 [40K,48K) -> 49152 bytes
__global__ void __launch_bounds__(128, 2)
attn_f16_kernel(const __half* __restrict__ qkv, __half* __restrict__ out) {
    extern __shared__ char smc[];
    uint32_t smb = (uint32_t)__cvta_generic_to_shared(smc);
    const int b = blockIdx.z, h = blockIdx.y;
    const int q0 = blockIdx.x * 128;
    const int tid = threadIdx.x;
    const int lane = tid & 31;
    const int w = tid >> 5;
    const int gid = lane >> 2, tig = lane & 3;
    const int arow = lane & 15, alch = lane >> 4;
    const int b_nrow = (lane & 7) + ((lane >> 4) << 3);
    const int b_kc = (lane & 8) >> 3;
    const float cscale = 0.125f * 1.4426950408889634f;   // scale * log2(e)

    for (int i = tid; i < 1024; i += 128) {
        int r = i >> 3, c = i & 7;
        const __half* src = qkv + ((size_t)(b * NN + q0 + r)) * C3 + h * DH + c * 8;
        CP_ASYNC16(smb + r * 128 + ((c ^ (r & 7)) << 4), src);
    }
    auto load_kv = [&](int buf, int kt) {
        uint32_t kb = smb + 16384 + buf * 8192;
        uint32_t vb = smb + 32768 + buf * 8192;
        for (int i = tid; i < 1024; i += 128) {
            int r = (i >> 3) & 63, c = i & 7;
            if (i < 512) {
                const __half* src = qkv + ((size_t)(b * NN + kt + r)) * C3 + CC + h * DH + c * 8;
                CP_ASYNC16(kb + r * 128 + ((c ^ (r & 7)) << 4), src);
            } else {
                const __half* src = qkv + ((size_t)(b * NN + kt + r)) * C3 + 2 * CC + h * DH + c * 8;
                CP_ASYNC16(vb + r * 128 + ((c ^ (r & 7)) << 4), src);
            }
        }
    };
    load_kv(0, 0);
    CP_COMMIT();

    float acco[2][8][4];
#pragma unroll
    for (int g = 0; g < 2; g++)
#pragma unroll
        for (int nt = 0; nt < 8; nt++)
#pragma unroll
            for (int j = 0; j < 4; j++) acco[g][nt][j] = 0.f;
    float m_[4] = {-1e30f, -1e30f, -1e30f, -1e30f};
    float l_[4] = {0.f, 0.f, 0.f, 0.f};

    const int NT = NN / 64;
    for (int it = 0; it < NT; it++) {
        int buf = it & 1;
        if (it + 1 < NT) {
            load_kv(buf ^ 1, (it + 1) * 64);
            CP_COMMIT();
            CP_WAIT(1);
        } else {
            CP_WAIT(0);
        }
        __syncthreads();

        uint32_t kb = smb + 16384 + buf * 8192;
        uint32_t vb = smb + 32768 + buf * 8192;

        float accs[2][8][4];
#pragma unroll
        for (int g = 0; g < 2; g++)
#pragma unroll
            for (int nt = 0; nt < 8; nt++)
#pragma unroll
                for (int j = 0; j < 4; j++) accs[g][nt][j] = 0.f;

#pragma unroll
        for (int ks = 0; ks < 4; ks++) {
            uint32_t aa[2][4];
#pragma unroll
            for (int g = 0; g < 2; g++) {
                int qr = w * 32 + g * 16 + arow;
                uint32_t aaddr = smb + qr * 128 + (((ks * 2 + alch) ^ (arow & 7)) << 4);
                LDMATRIX_X4(aa[g][0], aa[g][1], aa[g][2], aa[g][3], aaddr);
            }
#pragma unroll
            for (int p = 0; p < 4; p++) {
                int n = p * 16 + b_nrow;
                uint32_t baddr = kb + n * 128 + (((ks * 2 + b_kc) ^ (n & 7)) << 4);
                uint32_t f0, f1, f2, f3;
                LDMATRIX_X4(f0, f1, f2, f3, baddr);
#pragma unroll
                for (int g = 0; g < 2; g++) {
                    MMA_F16(accs[g][2*p][0], accs[g][2*p][1], accs[g][2*p][2], accs[g][2*p][3],
                            aa[g][0], aa[g][1], aa[g][2], aa[g][3], f0, f1);
                    MMA_F16(accs[g][2*p+1][0], accs[g][2*p+1][1], accs[g][2*p+1][2], accs[g][2*p+1][3],
                            aa[g][0], aa[g][1], aa[g][2], aa[g][3], f2, f3);
                }
            }
        }

        uint32_t p_lo[2][8], p_hi[2][8];
#pragma unroll
        for (int g = 0; g < 2; g++) {
            float mx0 = -1e30f, mx1 = -1e30f;
#pragma unroll
            for (int nt = 0; nt < 8; nt++) {
                mx0 = fmaxf(mx0, fmaxf(accs[g][nt][0], accs[g][nt][1]));
                mx1 = fmaxf(mx1, fmaxf(accs[g][nt][2], accs[g][nt][3]));
            }
            mx0 = fmaxf(mx0, __shfl_xor_sync(0xffffffffu, mx0, 1));
            mx0 = fmaxf(mx0, __shfl_xor_sync(0xffffffffu, mx0, 2));
            mx1 = fmaxf(mx1, __shfl_xor_sync(0xffffffffu, mx1, 1));
            mx1 = fmaxf(mx1, __shfl_xor_sync(0xffffffffu, mx1, 2));
            float mn0 = fmaxf(m_[2*g], mx0), mn1 = fmaxf(m_[2*g+1], mx1);
            float cr0 = exp2f((m_[2*g] - mn0) * cscale);
            float cr1 = exp2f((m_[2*g+1] - mn1) * cscale);
            float mn0c = mn0 * cscale, mn1c = mn1 * cscale;
            float s0 = 0.f, s1 = 0.f;
#pragma unroll
            for (int nt = 0; nt < 8; nt++) {
                float p0 = exp2f(fmaf(accs[g][nt][0], cscale, -mn0c));
                float p1 = exp2f(fmaf(accs[g][nt][1], cscale, -mn0c));
                float p2 = exp2f(fmaf(accs[g][nt][2], cscale, -mn1c));
                float p3 = exp2f(fmaf(accs[g][nt][3], cscale, -mn1c));
                s0 += p0 + p1; s1 += p2 + p3;
                __half2 lo = __floats2half2_rn(p0, p1);
                __half2 hi = __floats2half2_rn(p2, p3);
                p_lo[g][nt] = *(uint32_t*)&lo;
                p_hi[g][nt] = *(uint32_t*)&hi;
            }
            s0 += __shfl_xor_sync(0xffffffffu, s0, 1);
            s0 += __shfl_xor_sync(0xffffffffu, s0, 2);
            s1 += __shfl_xor_sync(0xffffffffu, s1, 1);
            s1 += __shfl_xor_sync(0xffffffffu, s1, 2);
            l_[2*g] = l_[2*g] * cr0 + s0;
            l_[2*g+1] = l_[2*g+1] * cr1 + s1;
            m_[2*g] = mn0; m_[2*g+1] = mn1;
#pragma unroll
            for (int nt = 0; nt < 8; nt++) {
                acco[g][nt][0] *= cr0; acco[g][nt][1] *= cr0;
                acco[g][nt][2] *= cr1; acco[g][nt][3] *= cr1;
            }
        }

#pragma unroll
        for (int ks = 0; ks < 4; ks++) {
#pragma unroll
            for (int p = 0; p < 4; p++) {
                int vr = ks * 16 + arow;
                int ch = p * 2 + alch;
                uint32_t baddr = vb + vr * 128 + ((ch ^ (vr & 7)) << 4);
                uint32_t f0, f1, f2, f3;
                LDMATRIX_X4_T(f0, f1, f2, f3, baddr);
#pragma unroll
                for (int g = 0; g < 2; g++) {
                    uint32_t a0 = p_lo[g][2 * ks],     a1 = p_hi[g][2 * ks];
                    uint32_t a2 = p_lo[g][2 * ks + 1], a3 = p_hi[g][2 * ks + 1];
                    MMA_F16(acco[g][2*p][0], acco[g][2*p][1], acco[g][2*p][2], acco[g][2*p][3],
                            a0, a1, a2, a3, f0, f1);
                    MMA_F16(acco[g][2*p+1][0], acco[g][2*p+1][1], acco[g][2*p+1][2], acco[g][2*p+1][3],
                            a0, a1, a2, a3, f2, f3);
                }
            }
        }
        __syncthreads();
    }

#pragma unroll
    for (int g = 0; g < 2; g++) {
        float inv0 = 1.f / l_[2*g], inv1 = 1.f / l_[2*g+1];
#pragma unroll
        for (int nt = 0; nt < 8; nt++) {
            int col = h * DH + nt * 8 + tig * 2;
            size_t r0 = (size_t)(b * NN + q0 + w * 32 + g * 16 + gid) * CC + col;
            __half2 v0 = __floats2half2_rn(acco[g][nt][0] * inv0, acco[g][nt][1] * inv0);
            *(__half2*)&out[r0] = v0;
            size_t r1 = (size_t)(b * NN + q0 + w * 32 + g * 16 + gid + 8) * CC + col;
            __half2 v1 = __floats2half2_rn(acco[g][nt][2] * inv1, acco[g][nt][3] * inv1);
            *(__half2*)&out[r1] = v1;
        }
    }
}

// ---------------- launch ----------------
extern "C" void kernel_launch(void* const* d_in, const int* in_sizes, int n_in,
                              void* d_out, int out_size) {
    const float* x      = (const float*)d_in[0];
    const float* pos    = (const float*)d_in[1];
    const float* Wqkv   = (const float*)d_in[2];
    const float* b_qkv  = (const float*)d_in[3];
    const float* lora_A = (const float*)d_in[4];
    const float* lora_B = (const float*)d_in[5];
    const float* Wproj  = (const float*)d_in[6];
    const float* b_proj = (const float*)d_in[7];
    const float* ln1_g  = (const float*)d_in[8];
    const float* ln1_b  = (const float*)d_in[9];
    const float* ln2_g  = (const float*)d_in[10];
    const float* ln2_b  = (const float*)d_in[11];
    const float* W1     = (const float*)d_in[12];
    const float* b1     = (const float*)d_in[13];
    const float* W2     = (const float*)d_in[14];
    const float* b2     = (const float*)d_in[15];
    float* out = (float*)d_out;

    __half *p_x1, *p_x2, *p_h, *p_qkv, *p_attn, *p_h2, *p_mlp;
    __half *p_wqkv, *p_wproj, *p_w1, *p_w2;
    cudaGetSymbolAddress((void**)&p_x1, g_x1);
    cudaGetSymbolAddress((void**)&p_x2, g_x2);
    cudaGetSymbolAddress((void**)&p_h, g_h);
    cudaGetSymbolAddress((void**)&p_qkv, g_qkv);
    cudaGetSymbolAddress((void**)&p_attn, g_attn);
    cudaGetSymbolAddress((void**)&p_h2, g_h2);
    cudaGetSymbolAddress((void**)&p_mlp, g_mlp);
    cudaGetSymbolAddress((void**)&p_wqkv, g_wqkv_h);
    cudaGetSymbolAddress((void**)&p_wproj, g_wproj_h);
    cudaGetSymbolAddress((void**)&p_w1, g_w1_h);
    cudaGetSymbolAddress((void**)&p_w2, g_w2_h);

    static cudaStream_t s2 = nullptr;
    static cudaEvent_t evFork = nullptr, evW0 = nullptr, evJoin = nullptr;
    static bool attr_set = false;
    if (!attr_set) {
        cudaFuncSetAttribute(gemm_f16_kernel,
                             cudaFuncAttributeMaxDynamicSharedMemorySize, 65536);
        cudaFuncSetAttribute(attn_f16_kernel,
                             cudaFuncAttributeMaxDynamicSharedMemorySize, 49152);
        cudaStreamCreateWithFlags(&s2, cudaStreamNonBlocking);
        cudaEventCreateWithFlags(&evFork, cudaEventDisableTiming);
        cudaEventCreateWithFlags(&evW0, cudaEventDisableTiming);
        cudaEventCreateWithFlags(&evJoin, cudaEventDisableTiming);
        attr_set = true;
    }

    // ---- fork: weight prep on side stream ----
    cudaEventRecord(evFork, 0);
    cudaStreamWaitEvent(s2, evFork, 0);
    wqkv_fold_f2h_kernel<<<(C3 * CC / 8 + 255) / 256, 256, 0, s2>>>(
        Wqkv, lora_A, lora_B, p_wqkv);
    cudaEventRecord(evW0, s2);
    f2h_kernel<<<(CC * CC / 8 + 255) / 256, 256, 0, s2>>>(Wproj, p_wproj, CC * CC / 8);
    f2h_kernel<<<(MLPD * CC / 8 + 255) / 256, 256, 0, s2>>>(W1, p_w1, MLPD * CC / 8);
    f2h_kernel<<<(CC * MLPD / 8 + 255) / 256, 256, 0, s2>>>(W2, p_w2, CC * MLPD / 8);
    cudaEventRecord(evJoin, s2);

    // 1) x1 = fp16(x + pos) ; h = LN1(x+pos) (fp16)
    addpos_ln_kernel<<<MM, 256>>>(x, pos, ln1_g, ln1_b, p_x1, p_h);

    // join Wqkv only
    cudaStreamWaitEvent(0, evW0, 0);

    // 2) qkv = h @ Wqkv_eff^T + b_qkv (LoRA folded; fp16 out)
    gemm_f16_kernel<<<dim3(C3 / 128, MM / 128), 256, 65536>>>(
        p_h, p_wqkv, b_qkv, nullptr, nullptr, p_qkv, MM, C3, CC, 0);

    // 3) attention (fp16 TC flash, 128-row q tiles, register P)
    attn_f16_kernel<<<dim3(NN / 128, HH, BB), 128, 49152>>>(p_qkv, p_attn);

    // join remaining weights before proj GEMM
    cudaStreamWaitEvent(0, evJoin, 0);

    // 4) x2 = fp16(x1 + attn @ Wproj^T + b_proj)
    gemm_f16_kernel<<<dim3(CC / 128, MM / 128), 256, 65536>>>(
        p_attn, p_wproj, b_proj, p_x1, nullptr, p_x2, MM, CC, CC, 0);

    // 5) h2 = LN2(x2) (fp16 in/out)
    ln_h_kernel<<<MM, 256>>>(p_x2, ln2_g, ln2_b, p_h2);

    // 6) mlp = gelu(h2 @ W1^T + b1) (fp16 out)
    gemm_f16_kernel<<<dim3(MLPD / 128, MM / 128), 256, 65536>>>(
        p_h2, p_w1, b1, nullptr, nullptr, p_mlp, MM, MLPD, CC, 1);

    // 7) out = x2 + mlp @ W2^T + b2 (fp32 out; res = fp16 x2)
    gemm_f16_kernel<<<dim3(CC / 128, MM / 128), 256, 65536>>>(
        p_mlp, p_w2, b2, p_x2, out, nullptr, MM, CC, MLPD, 0);
}

// round 15
// speedup vs baseline: 1.5253x; 1.5253x over previous
#include <cuda_runtime.h>
#include <cuda_fp16.h>
#include <math.h>
#include <stdint.h>

// Problem constants
#define BB 2
#define NN 2048
#define CC 1024
#define HH 16
#define DH 64
#define MLPD 4096
#define MM (BB*NN)          // 4096 tokens
#define C3 (3*CC)           // 3072

// ---------------- scratch (static device globals; no allocation) ----------------
__device__ float  g_x1[MM*CC];       // x + pos (fp32 residual)
__device__ float  g_x2[MM*CC];       // after attn residual (fp32)
__device__ __half g_h[MM*CC];        // LN1 out
__device__ __half g_qkv[MM*C3];      // qkv (lora folded into weights)
__device__ __half g_attn[MM*CC];     // attention out
__device__ __half g_h2[MM*CC];       // LN2 out
__device__ __half g_mlp[MM*MLPD];    // gelu(...)
__device__ __half g_wqkv_h[C3*CC];   // Wqkv + 0.25*B@A folded, fp16
__device__ __half g_wproj_h[CC*CC];
__device__ __half g_w1_h[MLPD*CC];
__device__ __half g_w2_h[CC*MLPD];

#define CP_ASYNC16(dst, src) \
    asm volatile("cp.async.ca.shared.global [%0], [%1], 16;" :: "r"(dst), "l"(src))
#define CP_COMMIT() asm volatile("cp.async.commit_group;")
#define CP_WAIT(n)  asm volatile("cp.async.wait_group %0;" :: "n"(n))

#define LDMATRIX_X4(r0, r1, r2, r3, addr) \
    asm volatile("ldmatrix.sync.aligned.m8n8.x4.shared.b16 {%0,%1,%2,%3}, [%4];" \
                 : "=r"(r0), "=r"(r1), "=r"(r2), "=r"(r3) : "r"(addr))
#define LDMATRIX_X4_T(r0, r1, r2, r3, addr) \
    asm volatile("ldmatrix.sync.aligned.m8n8.x4.trans.shared.b16 {%0,%1,%2,%3}, [%4];" \
                 : "=r"(r0), "=r"(r1), "=r"(r2), "=r"(r3) : "r"(addr))

#define MMA_F16(c0, c1, c2, c3, a0, a1, a2, a3, b0, b1) \
    asm volatile("mma.sync.aligned.m16n8k16.row.col.f32.f16.f16.f32 " \
                 "{%0,%1,%2,%3}, {%4,%5,%6,%7}, {%8,%9}, {%0,%1,%2,%3};" \
                 : "+f"(c0), "+f"(c1), "+f"(c2), "+f"(c3) \
                 : "r"(a0), "r"(a1), "r"(a2), "r"(a3), "r"(b0), "r"(b1))

// ---------------- fp32 -> fp16 weight conversion ----------------
__global__ void f2h_kernel(const float* __restrict__ in,
                           __half* __restrict__ out, int n8) {
    int i = blockIdx.x * blockDim.x + threadIdx.x;
    if (i < n8) {
        float4 a = ((const float4*)in)[2 * i];
        float4 b = ((const float4*)in)[2 * i + 1];
        __half2 h[4];
        h[0] = __floats2half2_rn(a.x, a.y);
        h[1] = __floats2half2_rn(a.z, a.w);
        h[2] = __floats2half2_rn(b.x, b.y);
        h[3] = __floats2half2_rn(b.z, b.w);
        ((uint4*)out)[i] = *(uint4*)h;
    }
}

// ---------------- Wqkv conversion with LoRA rank-4 fold ----------------
__global__ void wqkv_fold_f2h_kernel(const float* __restrict__ W,
                                     const float* __restrict__ loraA,   // [8,1024]
                                     const float* __restrict__ loraB,   // [2048,4]
                                     __half* __restrict__ out) {
    int idx = blockIdx.x * blockDim.x + threadIdx.x;   // < 3072*1024/8
    if (idx >= C3 * CC / 8) return;
    int i = idx >> 7;              // row 0..3071
    int j0 = (idx & 127) * 8;      // col block
    float4 a = ((const float4*)(W + (size_t)i * CC + j0))[0];
    float4 b = ((const float4*)(W + (size_t)i * CC + j0))[1];
    float w[8] = {a.x, a.y, a.z, a.w, b.x, b.y, b.z, b.w};
    int aoff = -1, brow = -1;
    if (i < CC)            { aoff = 0; brow = i; }
    else if (i >= 2 * CC)  { aoff = 4; brow = CC + (i - 2 * CC); }
    if (aoff >= 0) {
        float br[4];
#pragma unroll
        for (int r = 0; r < 4; r++) br[r] = loraB[brow * 4 + r];
#pragma unroll
        for (int jj = 0; jj < 8; jj++) {
            float d = 0.f;
#pragma unroll
            for (int r = 0; r < 4; r++)
                d = fmaf(br[r], loraA[(aoff + r) * CC + j0 + jj], d);
            w[jj] += 0.25f * d;
        }
    }
    __half2 h[4];
#pragma unroll
    for (int p = 0; p < 4; p++) h[p] = __floats2half2_rn(w[2 * p], w[2 * p + 1]);
    ((uint4*)out)[idx] = *(uint4*)h;
}

// ---------------- fused (x+pos) + LayerNorm -> fp16 (float4, shuffle reductions) ----------------
__global__ void addpos_ln_kernel(const float* __restrict__ x,
                                 const float* __restrict__ pos,
                                 const float* __restrict__ g,
                                 const float* __restrict__ b,
                                 float* __restrict__ x1out,
                                 __half* __restrict__ hout) {
    int row = blockIdx.x;
    int t = threadIdx.x;
    int warp = t >> 5, lane = t & 31;
    const float4* xr4 = (const float4*)(x + (size_t)row * CC);
    float4 v4 = xr4[t];
    if (pos) {
        float4 p4 = ((const float4*)(pos + (size_t)row * CC))[t];
        v4.x += p4.x; v4.y += p4.y; v4.z += p4.z; v4.w += p4.w;
    }
    if (x1out) ((float4*)(x1out + (size_t)row * CC))[t] = v4;

    __shared__ float swred[8];
    __shared__ float bc[2];
    float s = v4.x + v4.y + v4.z + v4.w;
#pragma unroll
    for (int o = 16; o > 0; o >>= 1) s += __shfl_xor_sync(0xffffffffu, s, o);
    if (lane == 0) swred[warp] = s;
    __syncthreads();
    if (t == 0) {
        float tot = 0.f;
#pragma unroll
        for (int w = 0; w < 8; w++) tot += swred[w];
        bc[0] = tot * (1.0f / CC);
    }
    __syncthreads();
    float mean = bc[0];
    float dx = v4.x - mean, dy = v4.y - mean, dz = v4.z - mean, dw = v4.w - mean;
    float sq = dx * dx + dy * dy + dz * dz + dw * dw;
#pragma unroll
    for (int o = 16; o > 0; o >>= 1) sq += __shfl_xor_sync(0xffffffffu, sq, o);
    if (lane == 0) swred[warp] = sq;
    __syncthreads();
    if (t == 0) {
        float tot = 0.f;
#pragma unroll
        for (int w = 0; w < 8; w++) tot += swred[w];
        bc[1] = rsqrtf(tot * (1.0f / CC) + 1e-5f);
    }
    __syncthreads();
    float rstd = bc[1];
    float4 g4 = ((const float4*)g)[t];
    float4 b4 = ((const float4*)b)[t];
    __half2 h01 = __floats2half2_rn(dx * rstd * g4.x + b4.x, dy * rstd * g4.y + b4.y);
    __half2 h23 = __floats2half2_rn(dz * rstd * g4.z + b4.z, dw * rstd * g4.w + b4.w);
    uint2 pk = make_uint2(*(uint32_t*)&h01, *(uint32_t*)&h23);
    ((uint2*)(hout + (size_t)row * CC))[t] = pk;
}

// ---------------- fp16 tensor-core GEMM (round-4 proven) ----------------
__global__ void __launch_bounds__(256)
gemm_f16_kernel(const __half* __restrict__ A, const __half* __restrict__ B,
                const float* __restrict__ bias, const float* __restrict__ res,
                float* __restrict__ outf, __half* __restrict__ outh,
                int M, int Ncols, int K, int act) {
    extern __shared__ char smc[];
    uint32_t smbase = (uint32_t)__cvta_generic_to_shared(smc);
    const int tid = threadIdx.x;
    const int lane = tid & 31;
    const int warp = tid >> 5;
    const int warp_m = warp & 1;
    const int warp_n = warp >> 1;
    const int bm = blockIdx.y * 128;
    const int bn = blockIdx.x * 128;

    const int a_lrow = lane & 15;
    const int a_lch  = lane >> 4;
    const int b_nrow = (lane & 7) + ((lane >> 4) << 3);
    const int b_kc   = (lane & 8) >> 3;

    float acc[4][4][4];
#pragma unroll
    for (int i = 0; i < 4; i++)
#pragma unroll
        for (int j = 0; j < 4; j++)
#pragma unroll
            for (int r = 0; r < 4; r++) acc[i][j][r] = 0.f;

    const int Ksteps = K >> 6;   // K/64

    auto load_tile = [&](int s, int kk) {
        uint32_t a_base = smbase + s * 16384;
        uint32_t b_base = smbase + 32768 + s * 16384;
#pragma unroll
        for (int i = 0; i < 4; i++) {
            int id = tid + i * 256;
            int row = id >> 3, ch = id & 7;
            const __half* srcA = A + (size_t)(bm + row) * K + kk + ch * 8;
            uint32_t dstA = a_base + row * 128 + ((ch ^ (row & 7)) << 4);
            CP_ASYNC16(dstA, srcA);
        }
#pragma unroll
        for (int i = 0; i < 4; i++) {
            int id = tid + i * 256;
            int row = id >> 3, ch = id & 7;
            const __half* srcB = B + (size_t)(bn + row) * K + kk + ch * 8;
            uint32_t dstB = b_base + row * 128 + ((ch ^ (row & 7)) << 4);
            CP_ASYNC16(dstB, srcB);
        }
    };

    load_tile(0, 0);
    CP_COMMIT();

    for (int s = 0; s < Ksteps; s++) {
        int buf = s & 1;
        if (s + 1 < Ksteps) {
            load_tile(buf ^ 1, (s + 1) << 6);
            CP_COMMIT();
            CP_WAIT(1);
        } else {
            CP_WAIT(0);
        }
        __syncthreads();

        uint32_t a_base = smbase + buf * 16384;
        uint32_t b_base = smbase + 32768 + buf * 16384;

#pragma unroll
        for (int ks = 0; ks < 4; ks++) {
            uint32_t af[4][4];
#pragma unroll
            for (int mt = 0; mt < 4; mt++) {
                int m = warp_m * 64 + mt * 16 + a_lrow;
                int chunk = ks * 2 + a_lch;
                uint32_t addr = a_base + m * 128 + ((chunk ^ (m & 7)) << 4);
                LDMATRIX_X4(af[mt][0], af[mt][1], af[mt][2], af[mt][3], addr);
            }
            uint32_t bf[2][4];
#pragma unroll
            for (int p = 0; p < 2; p++) {
                int n = warp_n * 32 + p * 16 + b_nrow;
                int chunk = ks * 2 + b_kc;
                uint32_t addr = b_base + n * 128 + ((chunk ^ (n & 7)) << 4);
                LDMATRIX_X4(bf[p][0], bf[p][1], bf[p][2], bf[p][3], addr);
            }
#pragma unroll
            for (int mt = 0; mt < 4; mt++)
#pragma unroll
                for (int nt = 0; nt < 4; nt++) {
                    uint32_t b0 = bf[nt >> 1][(nt & 1) * 2];
                    uint32_t b1 = bf[nt >> 1][(nt & 1) * 2 + 1];
                    MMA_F16(acc[mt][nt][0], acc[mt][nt][1], acc[mt][nt][2], acc[mt][nt][3],
                            af[mt][0], af[mt][1], af[mt][2], af[mt][3], b0, b1);
                }
        }
        __syncthreads();
    }

    const int gid = lane >> 2;
    const int tig = lane & 3;
#pragma unroll
    for (int mt = 0; mt < 4; mt++) {
#pragma unroll
        for (int nt = 0; nt < 4; nt++) {
            int col = bn + warp_n * 32 + nt * 8 + tig * 2;
            float bi0 = bias[col], bi1 = bias[col + 1];
#pragma unroll
            for (int half_i = 0; half_i < 2; half_i++) {
                int row = bm + warp_m * 64 + mt * 16 + gid + half_i * 8;
                float v0 = acc[mt][nt][half_i * 2 + 0] + bi0;
                float v1 = acc[mt][nt][half_i * 2 + 1] + bi1;
                if (act == 1) {
                    v0 = 0.5f * v0 * (1.0f + erff(v0 * 0.70710678118654752f));
                    v1 = 0.5f * v1 * (1.0f + erff(v1 * 0.70710678118654752f));
                }
                if (res) {
                    v0 += res[(size_t)row * Ncols + col];
                    v1 += res[(size_t)row * Ncols + col + 1];
                }
                if (outh) {
                    __half2 hv = __floats2half2_rn(v0, v1);
                    *(__half2*)&outh[(size_t)row * Ncols + col] = hv;
                } else {
                    float2 ov = make_float2(v0, v1);
                    *(float2*)&outf[(size_t)row * Ncols + col] = ov;
                }
            }
        }
    }
}

// ---------------- fp16 TC flash attention: 128 q-rows, 4 warps (32 q-rows/warp), register P ----------------
// smem: Q [0,16K) K0 [16K,24K) K1 [24K,32K) V0 [32K,40K) V1 [40K,48K) -> 49152 bytes
__global__ void __launch_bounds__(128, 2)
attn_f16_kernel(const __half* __restrict__ qkv, __half* __restrict__ out) {
    extern __shared__ char smc[];
    uint32_t smb = (uint32_t)__cvta_generic_to_shared(smc);
    const int b = blockIdx.z, h = blockIdx.y;
    const int q0 = blockIdx.x * 128;
    const int tid = threadIdx.x;
    const int lane = tid & 31;
    const int w = tid >> 5;
    const int gid = lane >> 2, tig = lane & 3;
    const int arow = lane & 15, alch = lane >> 4;
    const int b_nrow = (lane & 7) + ((lane >> 4) << 3);
    const int b_kc = (lane & 8) >> 3;
    const float cscale = 0.125f * 1.4426950408889634f;   // scale * log2(e)

    // stage Q: 128 rows (16 KB)
    for (int i = tid; i < 1024; i += 128) {
        int r = i >> 3, c = i & 7;
        const __half* src = qkv + ((size_t)(b * NN + q0 + r)) * C3 + h * DH + c * 8;
        CP_ASYNC16(smb + r * 128 + ((c ^ (r & 7)) << 4), src);
    }
    auto load_kv = [&](int buf, int kt) {
        uint32_t kb = smb + 16384 + buf * 8192;
        uint32_t vb = smb + 32768 + buf * 8192;
        for (int i = tid; i < 1024; i += 128) {
            int r = (i >> 3) & 63, c = i & 7;
            if (i < 512) {
                const __half* src = qkv + ((size_t)(b * NN + kt + r)) * C3 + CC + h * DH + c * 8;
                CP_ASYNC16(kb + r * 128 + ((c ^ (r & 7)) << 4), src);
            } else {
                const __half* src = qkv + ((size_t)(b * NN + kt + r)) * C3 + 2 * CC + h * DH + c * 8;
                CP_ASYNC16(vb + r * 128 + ((c ^ (r & 7)) << 4), src);
            }
        }
    };
    load_kv(0, 0);
    CP_COMMIT();

    float acco[2][8][4];
#pragma unroll
    for (int g = 0; g < 2; g++)
#pragma unroll
        for (int nt = 0; nt < 8; nt++)
#pragma unroll
            for (int j = 0; j < 4; j++) acco[g][nt][j] = 0.f;
    float m_[4] = {-1e30f, -1e30f, -1e30f, -1e30f};
    float l_[4] = {0.f, 0.f, 0.f, 0.f};

    const int NT = NN / 64;
    for (int it = 0; it < NT; it++) {
        int buf = it & 1;
        if (it + 1 < NT) {
            load_kv(buf ^ 1, (it + 1) * 64);
            CP_COMMIT();
            CP_WAIT(1);
        } else {
            CP_WAIT(0);
        }
        __syncthreads();

        uint32_t kb = smb + 16384 + buf * 8192;
        uint32_t vb = smb + 32768 + buf * 8192;

        // ---- S = Q K^T (both 16-row q groups share each K fragment) ----
        float accs[2][8][4];
#pragma unroll
        for (int g = 0; g < 2; g++)
#pragma unroll
            for (int nt = 0; nt < 8; nt++)
#pragma unroll
                for (int j = 0; j < 4; j++) accs[g][nt][j] = 0.f;

#pragma unroll
        for (int ks = 0; ks < 4; ks++) {
            uint32_t aa[2][4];
#pragma unroll
            for (int g = 0; g < 2; g++) {
                int qr = w * 32 + g * 16 + arow;
                uint32_t aaddr = smb + qr * 128 + (((ks * 2 + alch) ^ (arow & 7)) << 4);
                LDMATRIX_X4(aa[g][0], aa[g][1], aa[g][2], aa[g][3], aaddr);
            }
#pragma unroll
            for (int p = 0; p < 4; p++) {
                int n = p * 16 + b_nrow;
                uint32_t baddr = kb + n * 128 + (((ks * 2 + b_kc) ^ (n & 7)) << 4);
                uint32_t f0, f1, f2, f3;
                LDMATRIX_X4(f0, f1, f2, f3, baddr);
#pragma unroll
                for (int g = 0; g < 2; g++) {
                    MMA_F16(accs[g][2*p][0], accs[g][2*p][1], accs[g][2*p][2], accs[g][2*p][3],
                            aa[g][0], aa[g][1], aa[g][2], aa[g][3], f0, f1);
                    MMA_F16(accs[g][2*p+1][0], accs[g][2*p+1][1], accs[g][2*p+1][2], accs[g][2*p+1][3],
                            aa[g][0], aa[g][1], aa[g][2], aa[g][3], f2, f3);
                }
            }
        }

        // ---- online softmax (exp2 domain) + pack P into A-fragments ----
        uint32_t p_lo[2][8], p_hi[2][8];
#pragma unroll
        for (int g = 0; g < 2; g++) {
            float mx0 = -1e30f, mx1 = -1e30f;
#pragma unroll
            for (int nt = 0; nt < 8; nt++) {
                mx0 = fmaxf(mx0, fmaxf(accs[g][nt][0], accs[g][nt][1]));
                mx1 = fmaxf(mx1, fmaxf(accs[g][nt][2], accs[g][nt][3]));
            }
            mx0 = fmaxf(mx0, __shfl_xor_sync(0xffffffffu, mx0, 1));
            mx0 = fmaxf(mx0, __shfl_xor_sync(0xffffffffu, mx0, 2));
            mx1 = fmaxf(mx1, __shfl_xor_sync(0xffffffffu, mx1, 1));
            mx1 = fmaxf(mx1, __shfl_xor_sync(0xffffffffu, mx1, 2));
            float mn0 = fmaxf(m_[2*g], mx0), mn1 = fmaxf(m_[2*g+1], mx1);
            float cr0 = exp2f((m_[2*g] - mn0) * cscale);
            float cr1 = exp2f((m_[2*g+1] - mn1) * cscale);
            float mn0c = mn0 * cscale, mn1c = mn1 * cscale;
            float s0 = 0.f, s1 = 0.f;
#pragma unroll
            for (int nt = 0; nt < 8; nt++) {
                float p0 = exp2f(fmaf(accs[g][nt][0], cscale, -mn0c));
                float p1 = exp2f(fmaf(accs[g][nt][1], cscale, -mn0c));
                float p2 = exp2f(fmaf(accs[g][nt][2], cscale, -mn1c));
                float p3 = exp2f(fmaf(accs[g][nt][3], cscale, -mn1c));
                s0 += p0 + p1; s1 += p2 + p3;
                __half2 lo = __floats2half2_rn(p0, p1);
                __half2 hi = __floats2half2_rn(p2, p3);
                p_lo[g][nt] = *(uint32_t*)&lo;
                p_hi[g][nt] = *(uint32_t*)&hi;
            }
            s0 += __shfl_xor_sync(0xffffffffu, s0, 1);
            s0 += __shfl_xor_sync(0xffffffffu, s0, 2);
            s1 += __shfl_xor_sync(0xffffffffu, s1, 1);
            s1 += __shfl_xor_sync(0xffffffffu, s1, 2);
            l_[2*g] = l_[2*g] * cr0 + s0;
            l_[2*g+1] = l_[2*g+1] * cr1 + s1;
            m_[2*g] = mn0; m_[2*g+1] = mn1;
#pragma unroll
            for (int nt = 0; nt < 8; nt++) {
                acco[g][nt][0] *= cr0; acco[g][nt][1] *= cr0;
                acco[g][nt][2] *= cr1; acco[g][nt][3] *= cr1;
            }
        }

        // ---- O += P V (V fragments shared across both q groups) ----
#pragma unroll
        for (int ks = 0; ks < 4; ks++) {
#pragma unroll
            for (int p = 0; p < 4; p++) {
                int vr = ks * 16 + arow;
                int ch = p * 2 + alch;
                uint32_t baddr = vb + vr * 128 + ((ch ^ (vr & 7)) << 4);
                uint32_t f0, f1, f2, f3;
                LDMATRIX_X4_T(f0, f1, f2, f3, baddr);
#pragma unroll
                for (int g = 0; g < 2; g++) {
                    uint32_t a0 = p_lo[g][2 * ks],     a1 = p_hi[g][2 * ks];
                    uint32_t a2 = p_lo[g][2 * ks + 1], a3 = p_hi[g][2 * ks + 1];
                    MMA_F16(acco[g][2*p][0], acco[g][2*p][1], acco[g][2*p][2], acco[g][2*p][3],
                            a0, a1, a2, a3, f0, f1);
                    MMA_F16(acco[g][2*p+1][0], acco[g][2*p+1][1], acco[g][2*p+1][2], acco[g][2*p+1][3],
                            a0, a1, a2, a3, f2, f3);
                }
            }
        }
        __syncthreads();
    }

#pragma unroll
    for (int g = 0; g < 2; g++) {
        float inv0 = 1.f / l_[2*g], inv1 = 1.f / l_[2*g+1];
#pragma unroll
        for (int nt = 0; nt < 8; nt++) {
            int col = h * DH + nt * 8 + tig * 2;
            size_t r0 = (size_t)(b * NN + q0 + w * 32 + g * 16 + gid) * CC + col;
            __half2 v0 = __floats2half2_rn(acco[g][nt][0] * inv0, acco[g][nt][1] * inv0);
            *(__half2*)&out[r0] = v0;
            size_t r1 = (size_t)(b * NN + q0 + w * 32 + g * 16 + gid + 8) * CC + col;
            __half2 v1 = __floats2half2_rn(acco[g][nt][2] * inv1, acco[g][nt][3] * inv1);
            *(__half2*)&out[r1] = v1;
        }
    }
}

// ---------------- launch ----------------
extern "C" void kernel_launch(void* const* d_in, const int* in_sizes, int n_in,
                              void* d_out, int out_size) {
    const float* x      = (const float*)d_in[0];
    const float* pos    = (const float*)d_in[1];
    const float* Wqkv   = (const float*)d_in[2];
    const float* b_qkv  = (const float*)d_in[3];
    const float* lora_A = (const float*)d_in[4];
    const float* lora_B = (const float*)d_in[5];
    const float* Wproj  = (const float*)d_in[6];
    const float* b_proj = (const float*)d_in[7];
    const float* ln1_g  = (const float*)d_in[8];
    const float* ln1_b  = (const float*)d_in[9];
    const float* ln2_g  = (const float*)d_in[10];
    const float* ln2_b  = (const float*)d_in[11];
    const float* W1     = (const float*)d_in[12];
    const float* b1     = (const float*)d_in[13];
    const float* W2     = (const float*)d_in[14];
    const float* b2     = (const float*)d_in[15];
    float* out = (float*)d_out;

    float *p_x1, *p_x2;
    __half *p_h, *p_qkv, *p_attn, *p_h2, *p_mlp;
    __half *p_wqkv, *p_wproj, *p_w1, *p_w2;
    cudaGetSymbolAddress((void**)&p_x1, g_x1);
    cudaGetSymbolAddress((void**)&p_x2, g_x2);
    cudaGetSymbolAddress((void**)&p_h, g_h);
    cudaGetSymbolAddress((void**)&p_qkv, g_qkv);
    cudaGetSymbolAddress((void**)&p_attn, g_attn);
    cudaGetSymbolAddress((void**)&p_h2, g_h2);
    cudaGetSymbolAddress((void**)&p_mlp, g_mlp);
    cudaGetSymbolAddress((void**)&p_wqkv, g_wqkv_h);
    cudaGetSymbolAddress((void**)&p_wproj, g_wproj_h);
    cudaGetSymbolAddress((void**)&p_w1, g_w1_h);
    cudaGetSymbolAddress((void**)&p_w2, g_w2_h);

    static cudaStream_t s2 = nullptr;
    static cudaEvent_t evFork = nullptr, evW0 = nullptr, evJoin = nullptr;
    static bool attr_set = false;
    if (!attr_set) {
        cudaFuncSetAttribute(gemm_f16_kernel,
                             cudaFuncAttributeMaxDynamicSharedMemorySize, 65536);
        cudaFuncSetAttribute(attn_f16_kernel,
                             cudaFuncAttributeMaxDynamicSharedMemorySize, 49152);
        cudaStreamCreateWithFlags(&s2, cudaStreamNonBlocking);
        cudaEventCreateWithFlags(&evFork, cudaEventDisableTiming);
        cudaEventCreateWithFlags(&evW0, cudaEventDisableTiming);
        cudaEventCreateWithFlags(&evJoin, cudaEventDisableTiming);
        attr_set = true;
    }

    // ---- fork: weight prep on side stream ----
    cudaEventRecord(evFork, 0);
    cudaStreamWaitEvent(s2, evFork, 0);
    wqkv_fold_f2h_kernel<<<(C3 * CC / 8 + 255) / 256, 256, 0, s2>>>(
        Wqkv, lora_A, lora_B, p_wqkv);
    cudaEventRecord(evW0, s2);
    f2h_kernel<<<(CC * CC / 8 + 255) / 256, 256, 0, s2>>>(Wproj, p_wproj, CC * CC / 8);
    f2h_kernel<<<(MLPD * CC / 8 + 255) / 256, 256, 0, s2>>>(W1, p_w1, MLPD * CC / 8);
    f2h_kernel<<<(CC * MLPD / 8 + 255) / 256, 256, 0, s2>>>(W2, p_w2, CC * MLPD / 8);
    cudaEventRecord(evJoin, s2);

    // 1) x1 = x + pos ; h = LN1(x1) (fp16)
    addpos_ln_kernel<<<MM, 256>>>(x, pos, ln1_g, ln1_b, p_x1, p_h);

    // join Wqkv only
    cudaStreamWaitEvent(0, evW0, 0);

    // 2) qkv = h @ Wqkv_eff^T + b_qkv (LoRA folded; fp16 out)
    gemm_f16_kernel<<<dim3(C3 / 128, MM / 128), 256, 65536>>>(
        p_h, p_wqkv, b_qkv, nullptr, nullptr, p_qkv, MM, C3, CC, 0);

    // 3) attention (fp16 TC flash, 128-row q tiles, register P)
    attn_f16_kernel<<<dim3(NN / 128, HH, BB), 128, 49152>>>(p_qkv, p_attn);

    // join remaining weights before proj GEMM
    cudaStreamWaitEvent(0, evJoin, 0);

    // 4) x2 = x1 + attn @ Wproj^T + b_proj (fp32 out)
    gemm_f16_kernel<<<dim3(CC / 128, MM / 128), 256, 65536>>>(
        p_attn, p_wproj, b_proj, p_x1, p_x2, nullptr, MM, CC, CC, 0);

    // 5) h2 = LN2(x2) (fp16)
    addpos_ln_kernel<<<MM, 256>>>(p_x2, nullptr, ln2_g, ln2_b, nullptr, p_h2);

    // 6) mlp = gelu(h2 @ W1^T + b1) (fp16 out)
    gemm_f16_kernel<<<dim3(MLPD / 128, MM / 128), 256, 65536>>>(
        p_h2, p_w1, b1, nullptr, nullptr, p_mlp, MM, MLPD, CC, 1);

    // 7) out = x2 + mlp @ W2^T + b2 (fp32 out)
    gemm_f16_kernel<<<dim3(CC / 128, MM / 128), 256, 65536>>>(
        p_mlp, p_w2, b2, p_x2, out, nullptr, MM, CC, MLPD, 0);
}